// round 8
// baseline (speedup 1.0000x reference)
#include <cuda_runtime.h>
#include <cstdint>
#include <math.h>

// ---------------------------------------------------------------------------
// Problem constants
// ---------------------------------------------------------------------------
#define T_TOK   4096
#define H_DIM   2048
#define E_NUM   32
#define I_DIM   1024
#define IS_DIM  2048
#define TOPK    8
#define NGRP    8
#define TOPKG   4

#define NT_MAX  544            // 32768/64 + 32 experts worth of pad tiles
#define ROWS_MAX (NT_MAX * 64) // 34816

// GEMM tile config
#define BM 64
#define BN 64
#define BK 32
#define LDS 36                  // padded smem row stride (floats): conflict-free
#define TSZ (64 * LDS)          // 2304 floats per 64x32 tile

// ---------------------------------------------------------------------------
// Device scratch (static globals: sanctioned scratch mechanism)
// ---------------------------------------------------------------------------
__device__ float         g_Wdense[T_TOK * E_NUM];        // dense combine weights
__device__ unsigned char g_Slot[T_TOK * E_NUM];          // slot index per (t,e)
__device__ int           g_counts[E_NUM];
__device__ int           g_off[E_NUM];
__device__ int           g_tile_e[NT_MAX];
__device__ int           g_rtok[ROWS_MAX];
__device__ float         g_rw[ROWS_MAX];
__device__ unsigned char g_rslot[ROWS_MAX];
__device__ float         g_Hb[(size_t)ROWS_MAX * I_DIM];   // routed intermediate (~142MB)
__device__ float         g_Hs[(size_t)T_TOK * IS_DIM];     // shared intermediate (32MB)
__device__ float         g_Y[(size_t)T_TOK * TOPK * H_DIM];// per-slot routed outputs (256MB)

// ---------------------------------------------------------------------------
// Small helpers
// ---------------------------------------------------------------------------
__device__ __forceinline__ unsigned f2tf(float x) {
    unsigned r;
    asm("cvt.rna.tf32.f32 %0, %1;" : "=r"(r) : "f"(x));
    return r;
}

__device__ __forceinline__ void mma_tf32(float* c, const unsigned* a, const unsigned* b) {
    asm volatile(
        "mma.sync.aligned.m16n8k8.row.col.f32.tf32.tf32.f32 "
        "{%0,%1,%2,%3}, {%4,%5,%6,%7}, {%8,%9}, {%0,%1,%2,%3};\n"
        : "+f"(c[0]), "+f"(c[1]), "+f"(c[2]), "+f"(c[3])
        : "r"(a[0]), "r"(a[1]), "r"(a[2]), "r"(a[3]), "r"(b[0]), "r"(b[1]));
}

__device__ __forceinline__ void cp16(void* sptr, const void* gptr) {
    unsigned sa = (unsigned)__cvta_generic_to_shared(sptr);
    asm volatile("cp.async.cg.shared.global [%0], [%1], 16;\n" :: "r"(sa), "l"(gptr));
}

__device__ __forceinline__ float silu_f(float x) { return x / (1.f + __expf(-x)); }

// ---------------------------------------------------------------------------
// 0) clear combine-weight matrix + counts
// ---------------------------------------------------------------------------
__global__ void k_clear() {
    int i = blockIdx.x * blockDim.x + threadIdx.x;
    if (i < T_TOK * E_NUM) g_Wdense[i] = 0.f;
    if (i < E_NUM) g_counts[i] = 0;
}

// ---------------------------------------------------------------------------
// 1) router: logits + DeepSeek-V3 group top-k routing. One warp per token.
// ---------------------------------------------------------------------------
__global__ void __launch_bounds__(128) k_router(const float* __restrict__ X,
                                                const float* __restrict__ GW,
                                                const float* __restrict__ EB) {
    const int warp = threadIdx.x >> 5;
    const int lane = threadIdx.x & 31;
    const int t = blockIdx.x * 4 + warp;

    __shared__ float ssw[4][32];
    __shared__ float ssc[4][32];

    // lane = expert: dot(hidden[t], gate_w[lane]) over H=2048, 8 accumulators
    const float* x = X + (size_t)t * H_DIM;
    const float* g = GW + (size_t)lane * H_DIM;
    float a0=0.f,a1=0.f,a2=0.f,a3=0.f,a4=0.f,a5=0.f,a6=0.f,a7=0.f;
    for (int k = 0; k < H_DIM; k += 8) {
        float4 xv0 = *(const float4*)(x + k);
        float4 gv0 = *(const float4*)(g + k);
        float4 xv1 = *(const float4*)(x + k + 4);
        float4 gv1 = *(const float4*)(g + k + 4);
        a0 += xv0.x * gv0.x;  a1 += xv0.y * gv0.y;
        a2 += xv0.z * gv0.z;  a3 += xv0.w * gv0.w;
        a4 += xv1.x * gv1.x;  a5 += xv1.y * gv1.y;
        a6 += xv1.z * gv1.z;  a7 += xv1.w * gv1.w;
    }
    float logit = ((a0 + a4) + (a1 + a5)) + ((a2 + a6) + (a3 + a7));

    // sigmoid in double for a correctly-rounded fp32 score
    double scd = 1.0 / (1.0 + exp(-(double)logit));
    float sc = (float)scd;
    float sw = sc + EB[lane];
    ssw[warp][lane] = sw;
    ssc[warp][lane] = sc;
    __syncwarp();

    if (lane == 0) {
        const float* swp = ssw[warp];
        const float* scp = ssc[warp];
        // group scores: sum of top-2 within each group of 4
        float gsc[NGRP];
#pragma unroll
        for (int gg = 0; gg < NGRP; gg++) {
            float m1 = -1e30f, m2 = -1e30f;
#pragma unroll
            for (int j = 0; j < 4; j++) {
                float v = swp[gg * 4 + j];
                if (v > m1) { m2 = m1; m1 = v; }
                else if (v > m2) m2 = v;
            }
            gsc[gg] = m1 + m2;
        }
        // top-4 groups (strict > keeps lowest index on ties, like jax)
        unsigned gmask = 0;
        for (int it = 0; it < TOPKG; it++) {
            int bg = 0; float bv = -1e30f;
            for (int gg = 0; gg < NGRP; gg++)
                if (!((gmask >> gg) & 1) && gsc[gg] > bv) { bv = gsc[gg]; bg = gg; }
            gmask |= 1u << bg;
        }
        // top-8 experts among allowed groups
        int idx[TOPK]; float wsel[TOPK]; float wsum = 0.f;
        unsigned taken = 0;
        for (int it = 0; it < TOPK; it++) {
            int be = 0; float bv = -1e30f;
            for (int ee = 0; ee < E_NUM; ee++) {
                if (!((gmask >> (ee >> 2)) & 1)) continue;
                if ((taken >> ee) & 1) continue;
                if (swp[ee] > bv) { bv = swp[ee]; be = ee; }
            }
            taken |= 1u << be;
            idx[it] = be;
            wsel[it] = scp[be];
            wsum += scp[be];
        }
        float inv = 2.5f / (wsum + 1e-20f);
        for (int it = 0; it < TOPK; it++) {
            int ee = idx[it];
            g_Wdense[(size_t)t * E_NUM + ee] = wsel[it] * inv;
            g_Slot[(size_t)t * E_NUM + ee] = (unsigned char)it;
            atomicAdd(&g_counts[ee], 1);
        }
    }
}

// ---------------------------------------------------------------------------
// 2) offsets + tile map + row-array init (single block)
// ---------------------------------------------------------------------------
__global__ void k_offsets() {
    if (threadIdx.x == 0) {
        int cum = 0;
        for (int e = 0; e < E_NUM; e++) {
            g_off[e] = cum;
            cum += (g_counts[e] + 63) & ~63;
        }
        for (int tt = 0; tt < NT_MAX; tt++) g_tile_e[tt] = -1;
        for (int e = 0; e < E_NUM; e++) {
            int t0 = g_off[e] >> 6;
            int nt = (g_counts[e] + 63) >> 6;
            for (int i = 0; i < nt; i++) g_tile_e[t0 + i] = e;
        }
    }
    for (int i = threadIdx.x; i < ROWS_MAX; i += blockDim.x) {
        g_rtok[i] = -1;
        g_rw[i] = 0.f;
        g_rslot[i] = 0;
    }
}

// ---------------------------------------------------------------------------
// 3) scatter tokens to expert row lists (deterministic block scan; 1 blk/expert)
// ---------------------------------------------------------------------------
__global__ void __launch_bounds__(1024) k_scatter() {
    const int e = blockIdx.x;
    const int tid = threadIdx.x;
    const int base_t = tid * 4;

    float w[4]; int cnt = 0;
#pragma unroll
    for (int i = 0; i < 4; i++) {
        w[i] = g_Wdense[(size_t)(base_t + i) * E_NUM + e];
        cnt += (w[i] != 0.f);
    }
    const int lane = tid & 31, wid = tid >> 5;
    int incl = cnt;
#pragma unroll
    for (int d = 1; d < 32; d <<= 1) {
        int v = __shfl_up_sync(0xFFFFFFFFu, incl, d);
        if (lane >= d) incl += v;
    }
    __shared__ int wsum[32];
    if (lane == 31) wsum[wid] = incl;
    __syncthreads();
    if (wid == 0) {
        int v = wsum[lane];
#pragma unroll
        for (int d = 1; d < 32; d <<= 1) {
            int u = __shfl_up_sync(0xFFFFFFFFu, v, d);
            if (lane >= d) v += u;
        }
        wsum[lane] = v;
    }
    __syncthreads();
    int excl = incl - cnt + (wid ? wsum[wid - 1] : 0);
    int pos = g_off[e] + excl;
#pragma unroll
    for (int i = 0; i < 4; i++) {
        if (w[i] != 0.f) {
            g_rtok[pos] = base_t + i;
            g_rw[pos] = w[i];
            g_rslot[pos] = g_Slot[(size_t)(base_t + i) * E_NUM + e];
            pos++;
        }
    }
}

// ---------------------------------------------------------------------------
// 4) up-projection GEMM: H = silu(X W1^T) * (X W3^T), tf32 mma, cp.async 2-stage
//    routed=1: A rows gathered via g_rtok, per-tile expert; routed=0: shared.
// ---------------------------------------------------------------------------
__global__ void __launch_bounds__(128) k_up(const float* __restrict__ X,
                                            const float* __restrict__ W1b,
                                            const float* __restrict__ W3b,
                                            int K, int N, int routed) {
    extern __shared__ float sm[];
    const int bx = blockIdx.x, by = blockIdx.y;
    int e = 0;
    if (routed) { e = g_tile_e[by]; if (e < 0) return; }
    const size_t wstride = (size_t)N * K;
    const float* W1 = W1b + (size_t)e * wstride;
    const float* W3 = W3b + (size_t)e * wstride;
    float* Hout = routed ? g_Hb : g_Hs;

    const int tid = threadIdx.x;
    const int lane = tid & 31;
    const int warp = tid >> 5;
    const int wm = (warp >> 1) << 5;
    const int wn = (warp & 1) << 5;

    const int lrow = tid >> 3;
    const int lcol = (tid & 7) << 2;

    const float *ap[4], *b1p[4], *b3p[4];
#pragma unroll
    for (int i = 0; i < 4; i++) {
        int r = lrow + 16 * i;
        int grow = (by << 6) + r;
        int tok = routed ? g_rtok[grow] : grow;
        if (tok < 0) tok = 0;
        ap[i] = X + (size_t)tok * K + lcol;
        int bn = (bx << 6) + r;
        b1p[i] = W1 + (size_t)bn * K + lcol;
        b3p[i] = W3 + (size_t)bn * K + lcol;
    }

    float cg[2][4][4], cu[2][4][4];
#pragma unroll
    for (int mi = 0; mi < 2; mi++)
#pragma unroll
        for (int ni = 0; ni < 4; ni++)
#pragma unroll
            for (int q = 0; q < 4; q++) { cg[mi][ni][q] = 0.f; cu[mi][ni][q] = 0.f; }

    float* st0 = sm;
    float* st1 = sm + 3 * TSZ;
    const int NT = K >> 5;

    // prefetch stage 0
    {
        float* s = st0;
#pragma unroll
        for (int i = 0; i < 4; i++) {
            int r = lrow + 16 * i;
            cp16(s + r * LDS + lcol,            ap[i]);
            cp16(s + TSZ + r * LDS + lcol,      b1p[i]);
            cp16(s + 2 * TSZ + r * LDS + lcol,  b3p[i]);
        }
        asm volatile("cp.async.commit_group;\n");
    }

    for (int kt = 0; kt < NT; kt++) {
        if (kt + 1 < NT) {
            float* s = ((kt + 1) & 1) ? st1 : st0;
            int off = (kt + 1) << 5;
#pragma unroll
            for (int i = 0; i < 4; i++) {
                int r = lrow + 16 * i;
                cp16(s + r * LDS + lcol,           ap[i] + off);
                cp16(s + TSZ + r * LDS + lcol,     b1p[i] + off);
                cp16(s + 2 * TSZ + r * LDS + lcol, b3p[i] + off);
            }
            asm volatile("cp.async.commit_group;\n");
            asm volatile("cp.async.wait_group 1;\n");
        } else {
            asm volatile("cp.async.wait_group 0;\n");
        }
        __syncthreads();
        const float* As  = (kt & 1) ? st1 : st0;
        const float* B1s = As + TSZ;
        const float* B3s = As + 2 * TSZ;
#pragma unroll
        for (int kk = 0; kk < 32; kk += 8) {
            unsigned af[2][4];
#pragma unroll
            for (int mi = 0; mi < 2; mi++) {
                const float* p = As + (wm + mi * 16 + (lane >> 2)) * LDS + kk + (lane & 3);
                af[mi][0] = f2tf(p[0]);
                af[mi][1] = f2tf(p[8 * LDS]);
                af[mi][2] = f2tf(p[4]);
                af[mi][3] = f2tf(p[8 * LDS + 4]);
            }
            unsigned b1f[4][2], b3f[4][2];
#pragma unroll
            for (int ni = 0; ni < 4; ni++) {
                const float* p = B1s + (wn + ni * 8 + (lane >> 2)) * LDS + kk + (lane & 3);
                b1f[ni][0] = f2tf(p[0]);
                b1f[ni][1] = f2tf(p[4]);
                const float* q = B3s + (wn + ni * 8 + (lane >> 2)) * LDS + kk + (lane & 3);
                b3f[ni][0] = f2tf(q[0]);
                b3f[ni][1] = f2tf(q[4]);
            }
#pragma unroll
            for (int mi = 0; mi < 2; mi++)
#pragma unroll
                for (int ni = 0; ni < 4; ni++) {
                    mma_tf32(cg[mi][ni], af[mi], b1f[ni]);
                    mma_tf32(cu[mi][ni], af[mi], b3f[ni]);
                }
        }
        __syncthreads();
    }

    const int lr = lane >> 2, lc2 = (lane & 3) << 1;
#pragma unroll
    for (int mi = 0; mi < 2; mi++)
#pragma unroll
        for (int ni = 0; ni < 4; ni++)
#pragma unroll
            for (int h = 0; h < 2; h++) {
                int row = (by << 6) + wm + mi * 16 + lr + h * 8;
                int col = (bx << 6) + wn + ni * 8 + lc2;
                float g0 = cg[mi][ni][h * 2], g1 = cg[mi][ni][h * 2 + 1];
                float u0 = cu[mi][ni][h * 2], u1 = cu[mi][ni][h * 2 + 1];
                float2 v;
                v.x = silu_f(g0) * u0;
                v.y = silu_f(g1) * u1;
                *reinterpret_cast<float2*>(&Hout[(size_t)row * N + col]) = v;
            }
}

// ---------------------------------------------------------------------------
// 5) down-projection GEMM: Y = H W2^T, scaled/scattered.
//    routed=1: reads g_Hb, writes w * y into g_Y[token][slot];
//    routed=0: reads g_Hs, writes y straight to Outp (d_out).  N fixed = 2048.
// ---------------------------------------------------------------------------
__global__ void __launch_bounds__(128) k_down(const float* __restrict__ W2b,
                                              int K, int routed,
                                              float* __restrict__ Outp) {
    __shared__ float sm[2 * 2 * TSZ];
    const int bx = blockIdx.x, by = blockIdx.y;
    const int N = H_DIM;
    int e = 0;
    if (routed) { e = g_tile_e[by]; if (e < 0) return; }
    const float* W2 = W2b + (size_t)e * N * K;
    const float* Ain = routed ? g_Hb : g_Hs;

    const int tid = threadIdx.x;
    const int lane = tid & 31;
    const int warp = tid >> 5;
    const int wm = (warp >> 1) << 5;
    const int wn = (warp & 1) << 5;
    const int lrow = tid >> 3;
    const int lcol = (tid & 7) << 2;

    const float *ap[4], *bp[4];
#pragma unroll
    for (int i = 0; i < 4; i++) {
        int r = lrow + 16 * i;
        ap[i] = Ain + (size_t)((by << 6) + r) * K + lcol;
        bp[i] = W2 + (size_t)((bx << 6) + r) * K + lcol;
    }

    float cc[2][4][4];
#pragma unroll
    for (int mi = 0; mi < 2; mi++)
#pragma unroll
        for (int ni = 0; ni < 4; ni++)
#pragma unroll
            for (int q = 0; q < 4; q++) cc[mi][ni][q] = 0.f;

    float* st0 = sm;
    float* st1 = sm + 2 * TSZ;
    const int NT = K >> 5;
    {
        float* s = st0;
#pragma unroll
        for (int i = 0; i < 4; i++) {
            int r = lrow + 16 * i;
            cp16(s + r * LDS + lcol,       ap[i]);
            cp16(s + TSZ + r * LDS + lcol, bp[i]);
        }
        asm volatile("cp.async.commit_group;\n");
    }
    for (int kt = 0; kt < NT; kt++) {
        if (kt + 1 < NT) {
            float* s = ((kt + 1) & 1) ? st1 : st0;
            int off = (kt + 1) << 5;
#pragma unroll
            for (int i = 0; i < 4; i++) {
                int r = lrow + 16 * i;
                cp16(s + r * LDS + lcol,       ap[i] + off);
                cp16(s + TSZ + r * LDS + lcol, bp[i] + off);
            }
            asm volatile("cp.async.commit_group;\n");
            asm volatile("cp.async.wait_group 1;\n");
        } else {
            asm volatile("cp.async.wait_group 0;\n");
        }
        __syncthreads();
        const float* As = (kt & 1) ? st1 : st0;
        const float* Bs = As + TSZ;
#pragma unroll
        for (int kk = 0; kk < 32; kk += 8) {
            unsigned af[2][4];
#pragma unroll
            for (int mi = 0; mi < 2; mi++) {
                const float* p = As + (wm + mi * 16 + (lane >> 2)) * LDS + kk + (lane & 3);
                af[mi][0] = f2tf(p[0]);
                af[mi][1] = f2tf(p[8 * LDS]);
                af[mi][2] = f2tf(p[4]);
                af[mi][3] = f2tf(p[8 * LDS + 4]);
            }
            unsigned bf[4][2];
#pragma unroll
            for (int ni = 0; ni < 4; ni++) {
                const float* p = Bs + (wn + ni * 8 + (lane >> 2)) * LDS + kk + (lane & 3);
                bf[ni][0] = f2tf(p[0]);
                bf[ni][1] = f2tf(p[4]);
            }
#pragma unroll
            for (int mi = 0; mi < 2; mi++)
#pragma unroll
                for (int ni = 0; ni < 4; ni++)
                    mma_tf32(cc[mi][ni], af[mi], bf[ni]);
        }
        __syncthreads();
    }

    const int lr = lane >> 2, lc2 = (lane & 3) << 1;
#pragma unroll
    for (int mi = 0; mi < 2; mi++)
#pragma unroll
        for (int ni = 0; ni < 4; ni++)
#pragma unroll
            for (int h = 0; h < 2; h++) {
                int row = (by << 6) + wm + mi * 16 + lr + h * 8;
                int col = (bx << 6) + wn + ni * 8 + lc2;
                float c0 = cc[mi][ni][h * 2], c1 = cc[mi][ni][h * 2 + 1];
                if (routed) {
                    int tok = g_rtok[row];
                    if (tok >= 0) {
                        float w = g_rw[row];
                        int slot = g_rslot[row];
                        float2 v; v.x = w * c0; v.y = w * c1;
                        *reinterpret_cast<float2*>(
                            &g_Y[((size_t)tok * TOPK + slot) * H_DIM + col]) = v;
                    }
                } else {
                    float2 v; v.x = c0; v.y = c1;
                    *reinterpret_cast<float2*>(&Outp[(size_t)row * H_DIM + col]) = v;
                }
            }
}

// ---------------------------------------------------------------------------
// 6) combine: out += sum over 8 routed slots (shared output already in out)
// ---------------------------------------------------------------------------
__global__ void k_combine(float* __restrict__ out) {
    int i = blockIdx.x * blockDim.x + threadIdx.x;  // over T*H/4 = 2,097,152
    const float4* Y4 = reinterpret_cast<const float4*>(g_Y);
    float4* O4 = reinterpret_cast<float4*>(out);
    int t = i >> 9;       // i / (2048/4)
    int c = i & 511;
    float4 acc = O4[i];
    const float4* yb = Y4 + ((size_t)t * TOPK) * 512 + c;
#pragma unroll
    for (int s = 0; s < TOPK; s++) {
        float4 v = yb[(size_t)s * 512];
        acc.x += v.x; acc.y += v.y; acc.z += v.z; acc.w += v.w;
    }
    O4[i] = acc;
}

// ---------------------------------------------------------------------------
// Launch
// ---------------------------------------------------------------------------
extern "C" void kernel_launch(void* const* d_in, const int* in_sizes, int n_in,
                              void* d_out, int out_size) {
    const float* hs  = (const float*)d_in[0];
    const float* gw  = (const float*)d_in[1];
    const float* eb  = (const float*)d_in[2];
    const float* w1  = (const float*)d_in[3];
    const float* w3  = (const float*)d_in[4];
    const float* w2  = (const float*)d_in[5];
    const float* sw1 = (const float*)d_in[6];
    const float* sw3 = (const float*)d_in[7];
    const float* sw2 = (const float*)d_in[8];
    float* out = (float*)d_out;

    cudaFuncSetAttribute((const void*)k_up,
                         cudaFuncAttributeMaxDynamicSharedMemorySize,
                         6 * TSZ * (int)sizeof(float));

    k_clear<<<512, 256>>>();
    k_router<<<T_TOK / 4, 128>>>(hs, gw, eb);
    k_offsets<<<1, 1024>>>();
    k_scatter<<<E_NUM, 1024>>>();

    // routed experts
    k_up<<<dim3(I_DIM / BN, NT_MAX), 128, 6 * TSZ * sizeof(float)>>>(
        hs, w1, w3, H_DIM, I_DIM, 1);
    k_down<<<dim3(H_DIM / BN, NT_MAX), 128>>>(w2, I_DIM, 1, nullptr);

    // shared expert (writes d_out directly)
    k_up<<<dim3(IS_DIM / BN, T_TOK / BM), 128, 6 * TSZ * sizeof(float)>>>(
        hs, sw1, sw3, H_DIM, IS_DIM, 0);
    k_down<<<dim3(H_DIM / BN, T_TOK / BM), 128>>>(sw2, IS_DIM, 0, out);

    // final combine
    k_combine<<<(T_TOK * H_DIM / 4) / 256, 256>>>(out);

    (void)in_sizes; (void)n_in; (void)out_size;
}